// round 6
// baseline (speedup 1.0000x reference)
#include <cuda_runtime.h>
#include <cuda_bf16.h>

// Fixed problem shape: B=8, R=C=1024, instance ids in [0,16).
static constexpr int RDIM = 1024;
static constexpr int CDIM = 1024;
static constexpr int PER_BATCH = RDIM * CDIM;            // 2^20 pixels
static constexpr int BATCH = 8;
static constexpr int MAX_INST = 16;
static constexpr int NPIX = BATCH * PER_BATCH;           // 2^23
static constexpr int NVEC_B = PER_BATCH / 4;             // 262144 vec4 per batch

// Kernel 1: 256-thread blocks, 8 CTAs/SM target, one wave of 1152 blocks.
static constexpr int BLKS_PER_B = 144;
static constexpr int TPB1 = 256;
static constexpr int CHUNK1 = (NVEC_B + BLKS_PER_B - 1) / BLKS_PER_B;  // 1821
// Kernel 3: 2 vec4 (8 px) per thread.
static constexpr int TPB3 = 256;
static constexpr int VPT3 = 2;
static constexpr int GRID3 = (NPIX / 4) / (TPB3 * VPT3);               // 4096

// Scratch (static device globals). Plain-stored every launch — replay-safe.
__device__ int           g_part[BATCH * BLKS_PER_B][MAX_INST];
__device__ float         g_inv[BATCH * MAX_INST];
__device__ unsigned char g_plane[NPIX];   // byte = raw_gt | (valid << 4)

__device__ __forceinline__ float sigmoidf_fast(float x) {
    return 1.0f / (1.0f + __expf(-x));
}

// ---- Kernel 1: atomic-free per-(batch,instance) counts + combined byte plane
__global__ void __launch_bounds__(TPB1, 8) pc_count_kernel(
    const int* __restrict__ nz, const int* __restrict__ gt)
{
    __shared__ unsigned long long wcnt[TPB1 / 32][4];

    const int tid  = threadIdx.x;
    const int wid  = tid >> 5;
    const int lane = tid & 31;
    const int b    = blockIdx.y;
    const int vbase = blockIdx.x * CHUNK1;
    const int vend  = min(vbase + CHUNK1, NVEC_B);
    const long long batch_off = (long long)b << 20;

    // byte-packed per-thread counters: ids 0..7 in lo, 8..15 in hi
    unsigned long long lo = 0ULL, hi = 0ULL;

    for (int v = vbase + tid; v < vend; v += TPB1) {
        const long long i0 = batch_off + (long long)v * 4;
        const int4 nz4 = *reinterpret_cast<const int4*>(nz + i0);
        const int4 gt4 = *reinterpret_cast<const int4*>(gt + i0);

        // gather low bytes: gp byte k = gt of pixel k; np likewise (values fit a byte)
        const unsigned g01 = __byte_perm((unsigned)gt4.x, (unsigned)gt4.y, 0x0040);
        const unsigned g23 = __byte_perm((unsigned)gt4.z, (unsigned)gt4.w, 0x0040);
        const unsigned gp  = __byte_perm(g01, g23, 0x5410);
        const unsigned n01 = __byte_perm((unsigned)nz4.x, (unsigned)nz4.y, 0x0040);
        const unsigned n23 = __byte_perm((unsigned)nz4.z, (unsigned)nz4.w, 0x0040);
        const unsigned np  = __byte_perm(n01, n23, 0x5410);

        // per-byte: g>0 <=> bit4 of (g+15);  nz is 0/1 so nz<<4 is the other bit
        const unsigned vmask = ((gp + 0x0F0F0F0Fu) & 0x10101010u) & (np << 4);
        *reinterpret_cast<unsigned int*>(g_plane + i0) = gp | vmask;

        // masked ids: byte = g if valid else 0 (id-0 counter is a harmless sink)
        const unsigned mg = gp & ((vmask >> 4) * 0xFFu);

        #pragma unroll
        for (int k = 0; k < 4; ++k) {
            const int m = (int)((mg >> (8 * k)) & 0xFFu);
            const unsigned long long inc = 1ULL << ((m & 7) * 8);
            if (m < 8) lo += inc; else hi += inc;
        }
    }

    // Expand byte counters to 16-bit fields (max 32 px/thread/id * 32 lanes)
    const unsigned long long M = 0x00FF00FF00FF00FFULL;
    unsigned long long v0 = lo & M;          // ids 0,2,4,6
    unsigned long long v1 = (lo >> 8) & M;   // ids 1,3,5,7
    unsigned long long v2 = hi & M;          // ids 8,10,12,14
    unsigned long long v3 = (hi >> 8) & M;   // ids 9,11,13,15

    #pragma unroll
    for (int s = 16; s > 0; s >>= 1) {
        v0 += __shfl_xor_sync(0xffffffffu, v0, s);
        v1 += __shfl_xor_sync(0xffffffffu, v1, s);
        v2 += __shfl_xor_sync(0xffffffffu, v2, s);
        v3 += __shfl_xor_sync(0xffffffffu, v3, s);
    }
    if (lane == 0) {
        wcnt[wid][0] = v0; wcnt[wid][1] = v1; wcnt[wid][2] = v2; wcnt[wid][3] = v3;
    }
    __syncthreads();

    if (tid < MAX_INST) {
        const int id = tid;
        const int vec   = (((id >= 8) ? 2 : 0) | (id & 1));
        const int shift = ((id & 7) >> 1) * 16;
        int s = 0;
        #pragma unroll
        for (int w = 0; w < TPB1 / 32; ++w)
            s += (int)((wcnt[w][vec] >> shift) & 0xFFFFULL);
        g_part[b * BLKS_PER_B + blockIdx.x][id] = s;
    }
}

// ---- Kernel 2: reduce partial histograms per batch -> inv_size table ----
__global__ void __launch_bounds__(128) pc_reduce_kernel()
{
    const int tid = threadIdx.x;          // 0..127 = b*16 + id
    const int b = tid >> 4, id = tid & 15;
    int s = 0;
    #pragma unroll 8
    for (int k = 0; k < BLKS_PER_B; ++k) s += g_part[b * BLKS_PER_B + k][id];
    g_inv[tid] = 1.0f / fmaxf((float)s, 1.0f);
}

// ---- Kernel 3: per-pixel weights; combined plane for stream AND gather ----
__global__ void __launch_bounds__(TPB3) pc_main_kernel(
    const float* __restrict__ pred,
    const float* __restrict__ off,     // (B, 2, R, C)
    float*       __restrict__ out_pw,  // (B, R, C)
    float*       __restrict__ out_ow)  // (B, 2, R, C)
{
    const int vb = blockIdx.x * (TPB3 * VPT3) + threadIdx.x;

    // Front-load all global reads (high MLP), then compute.
    unsigned int packed[VPT3];
    float4 pr4[VPT3], oy4[VPT3], ox4[VPT3];
    long long i0s[VPT3], obs[VPT3];

    #pragma unroll
    for (int j = 0; j < VPT3; ++j) {
        const int v = vb + j * TPB3;
        const long long i0 = (long long)v * 4;
        const int b   = (int)(i0 >> 20);
        const int rem = (int)(i0 & (PER_BATCH - 1));
        const long long ob = ((long long)b * 2) * PER_BATCH + rem;
        i0s[j] = i0; obs[j] = ob;
        packed[j] = *reinterpret_cast<const unsigned int*>(g_plane + i0);
        pr4[j] = *reinterpret_cast<const float4*>(pred + i0);
        oy4[j] = *reinterpret_cast<const float4*>(off + ob);
        ox4[j] = *reinterpret_cast<const float4*>(off + ob + PER_BATCH);
    }

    #pragma unroll
    for (int j = 0; j < VPT3; ++j) {
        const long long i0 = i0s[j];
        const long long ob = obs[j];
        const int b   = (int)(i0 >> 20);
        const int rem = (int)(i0 & (PER_BATCH - 1));
        const int r   = rem >> 10;
        const int c0  = rem & (CDIM - 1);

        const unsigned char* __restrict__ plane_b = g_plane + ((long long)b << 20);
        const float* __restrict__ inv_b = g_inv + b * MAX_INST;

        const float prs[4] = {pr4[j].x, pr4[j].y, pr4[j].z, pr4[j].w};
        const float oys[4] = {oy4[j].x, oy4[j].y, oy4[j].z, oy4[j].w};
        const float oxs[4] = {ox4[j].x, ox4[j].y, ox4[j].z, ox4[j].w};
        const float rf = (float)r;

        float pw[4], w0[4], w1[4];
        #pragma unroll
        for (int k = 0; k < 4; ++k) {
            const unsigned s = (packed[j] >> (8 * k)) & 0xFFu;
            const int g = (int)(s & 0xFu);
            float w = 0.0f, agree_w = 0.0f;
            if (s & 0x10u) {                         // valid
                w = __ldg(&inv_b[g]);
                // round-half-to-even matches jnp.round
                float tyf = rintf(rf + oys[k]);
                float txf = rintf((float)(c0 + k) + oxs[k]);
                tyf = fminf(fmaxf(tyf, 0.0f), (float)(RDIM - 1));
                txf = fminf(fmaxf(txf, 0.0f), (float)(CDIM - 1));
                const unsigned tb = __ldg(&plane_b[((int)tyf << 10) + (int)txf]);
                agree_w = ((int)(tb & 0xFu) == g) ? w : 0.0f;
            }
            pw[k] = w * sigmoidf_fast(prs[k]);
            w0[k] = agree_w * oys[k];
            w1[k] = agree_w * oxs[k];
        }

        *reinterpret_cast<float4*>(out_pw + i0)             = make_float4(pw[0], pw[1], pw[2], pw[3]);
        *reinterpret_cast<float4*>(out_ow + ob)             = make_float4(w0[0], w0[1], w0[2], w0[3]);
        *reinterpret_cast<float4*>(out_ow + ob + PER_BATCH) = make_float4(w1[0], w1[1], w1[2], w1[3]);
    }
}

extern "C" void kernel_launch(void* const* d_in, const int* in_sizes, int n_in,
                              void* d_out, int out_size) {
    const int*   nz   = (const int*)  d_in[0];  // non_zeros_map (B,R,C) int32
    const float* pred = (const float*)d_in[1];  // pixel_pred    (B,R,C) f32
    const float* off  = (const float*)d_in[2];  // offset_pred   (B,2,R,C) f32
    const int*   gt   = (const int*)  d_in[3];  // pixel_gt      (B,R,C) int32

    const long long N = in_sizes[0];            // B*R*C
    float* out_pw = (float*)d_out;
    float* out_ow = (float*)d_out + N;

    dim3 grid1(BLKS_PER_B, BATCH);
    pc_count_kernel<<<grid1, TPB1>>>(nz, gt);
    pc_reduce_kernel<<<1, 128>>>();
    pc_main_kernel<<<GRID3, TPB3>>>(pred, off, out_pw, out_ow);
}

// round 7
// speedup vs baseline: 1.1886x; 1.1886x over previous
#include <cuda_runtime.h>
#include <cuda_bf16.h>

// Fixed problem shape: B=8, R=C=1024, instance ids in [0,16).
static constexpr int RDIM = 1024;
static constexpr int CDIM = 1024;
static constexpr int PER_BATCH = RDIM * CDIM;            // 2^20 pixels
static constexpr int BATCH = 8;
static constexpr int MAX_INST = 16;
static constexpr int NPIX = BATCH * PER_BATCH;           // 2^23
static constexpr int NVEC_B = PER_BATCH / 4;             // 262144 vec4 per batch

// Kernel 1: 256 threads x 4 vec4/thread, front-loaded loads.
static constexpr int TPB1 = 256;
static constexpr int VPT1 = 4;
static constexpr int VEC_PER_BLK1 = TPB1 * VPT1;                    // 1024
static constexpr int BLKS_PER_B = NVEC_B / VEC_PER_BLK1;            // 256
// Kernel 3: R4-proven config (1 vec4/thread).
static constexpr int TPB3 = 256;
static constexpr int GRID3 = (NPIX / 4) / TPB3;                     // 8192

// Scratch (static device globals). Plain-stored every launch — replay-safe.
__device__ int           g_part[BATCH * BLKS_PER_B][MAX_INST];
__device__ float         g_inv[BATCH * MAX_INST];
__device__ unsigned char g_plane[NPIX];   // byte = raw_gt | (valid << 4)

__device__ __forceinline__ float sigmoidf_fast(float x) {
    return 1.0f / (1.0f + __expf(-x));
}

// ---- Kernel 1: counts + combined byte plane, MLP-maximized ----
__global__ void __launch_bounds__(TPB1, 4) pc_count_kernel(
    const int* __restrict__ nz, const int* __restrict__ gt)
{
    __shared__ unsigned long long wcnt[TPB1 / 32][4];

    const int tid  = threadIdx.x;
    const int wid  = tid >> 5;
    const int lane = tid & 31;
    const int b    = blockIdx.y;
    const long long base = ((long long)b << 20)
                         + (long long)(blockIdx.x * VEC_PER_BLK1 + tid) * 4;

    // Front-load ALL global reads: 8 outstanding LDG.128 before any compute.
    int4 nzv[VPT1], gtv[VPT1];
    #pragma unroll
    for (int j = 0; j < VPT1; ++j) {
        const long long i0 = base + (long long)j * (TPB1 * 4);
        nzv[j] = *reinterpret_cast<const int4*>(nz + i0);
        gtv[j] = *reinterpret_cast<const int4*>(gt + i0);
    }

    // Two independent 4-bit-field accumulators (id*4 bit position).
    // Each covers 2 vec4 = 8 pixels -> max 8 per field < 16: no overflow.
    unsigned long long c01 = 0ULL, c23 = 0ULL;

    #pragma unroll
    for (int j = 0; j < VPT1; ++j) {
        const long long i0 = base + (long long)j * (TPB1 * 4);
        // gather low bytes of the 4 ints (values fit a byte)
        const unsigned g01 = __byte_perm((unsigned)gtv[j].x, (unsigned)gtv[j].y, 0x0040);
        const unsigned g23 = __byte_perm((unsigned)gtv[j].z, (unsigned)gtv[j].w, 0x0040);
        const unsigned gp  = __byte_perm(g01, g23, 0x5410);
        const unsigned n01 = __byte_perm((unsigned)nzv[j].x, (unsigned)nzv[j].y, 0x0040);
        const unsigned n23 = __byte_perm((unsigned)nzv[j].z, (unsigned)nzv[j].w, 0x0040);
        const unsigned np  = __byte_perm(n01, n23, 0x5410);

        // per-byte: g>0 <=> bit4 of (g+15);  nz is 0/1 so nz<<4 is the other bit
        const unsigned vmask = ((gp + 0x0F0F0F0Fu) & 0x10101010u) & (np << 4);
        *reinterpret_cast<unsigned int*>(g_plane + i0) = gp | vmask;

        // masked ids: byte = g if valid else 0 (field 0 is a harmless sink)
        const unsigned mg = gp & ((vmask >> 4) * 0xFFu);

        unsigned long long& c = (j < 2) ? c01 : c23;
        c += 1ULL << ((mg << 2) & 0x3Cu);            // k=0: m*4
        c += 1ULL << ((mg >> 6) & 0x3Cu);            // k=1
        c += 1ULL << ((mg >> 14) & 0x3Cu);           // k=2
        c += 1ULL << ((mg >> 22) & 0x3Cu);           // k=3
    }

    // Expand 4-bit fields -> 8-bit (even/odd id split), combine, -> 16-bit.
    const unsigned long long M4 = 0x0F0F0F0F0F0F0F0FULL;
    const unsigned long long M8 = 0x00FF00FF00FF00FFULL;
    const unsigned long long A  = (c01 & M4) + (c23 & M4);               // ids 0,2,..,14
    const unsigned long long Bv = ((c01 >> 4) & M4) + ((c23 >> 4) & M4); // ids 1,3,..,15
    unsigned long long v0 = A & M8;          // ids 0,4,8,12
    unsigned long long v1 = (A >> 8) & M8;   // ids 2,6,10,14
    unsigned long long v2 = Bv & M8;         // ids 1,5,9,13
    unsigned long long v3 = (Bv >> 8) & M8;  // ids 3,7,11,15

    #pragma unroll
    for (int s = 16; s > 0; s >>= 1) {
        v0 += __shfl_xor_sync(0xffffffffu, v0, s);
        v1 += __shfl_xor_sync(0xffffffffu, v1, s);
        v2 += __shfl_xor_sync(0xffffffffu, v2, s);
        v3 += __shfl_xor_sync(0xffffffffu, v3, s);
    }
    if (lane == 0) {
        wcnt[wid][0] = v0; wcnt[wid][1] = v1; wcnt[wid][2] = v2; wcnt[wid][3] = v3;
    }
    __syncthreads();

    if (tid < MAX_INST) {
        const int id = tid;
        const int vec   = (id & 1) ? ((id & 2) ? 3 : 2) : ((id & 2) ? 1 : 0);
        const int shift = (id >> 2) * 16;
        int s = 0;
        #pragma unroll
        for (int w = 0; w < TPB1 / 32; ++w)
            s += (int)((wcnt[w][vec] >> shift) & 0xFFFFULL);
        g_part[b * BLKS_PER_B + blockIdx.x][id] = s;
    }
}

// ---- Kernel 2: reduce 256 partials per batch -> inv_size table ----
__global__ void __launch_bounds__(1024) pc_reduce_kernel()
{
    __shared__ int acc[128][8];
    const int tid  = threadIdx.x;
    const int slot = tid >> 3;             // 0..127 = b*16 + id
    const int lane = tid & 7;
    const int b = slot >> 4, id = slot & 15;
    int s = 0;
    #pragma unroll 8
    for (int k = lane; k < BLKS_PER_B; k += 8) s += g_part[b * BLKS_PER_B + k][id];
    acc[slot][lane] = s;
    __syncthreads();
    if (lane == 0) {
        int tot = 0;
        #pragma unroll
        for (int l = 0; l < 8; ++l) tot += acc[slot][l];
        g_inv[slot] = 1.0f / fmaxf((float)tot, 1.0f);
    }
}

// ---- Kernel 3: per-pixel weights (R4-proven form) ----
__global__ void __launch_bounds__(TPB3) pc_main_kernel(
    const float* __restrict__ pred,
    const float* __restrict__ off,     // (B, 2, R, C)
    float*       __restrict__ out_pw,  // (B, R, C)
    float*       __restrict__ out_ow)  // (B, 2, R, C)
{
    const int v = blockIdx.x * TPB3 + threadIdx.x;
    const long long i0 = (long long)v * 4;
    const int b   = (int)(i0 >> 20);
    const int rem = (int)(i0 & (PER_BATCH - 1));
    const int r   = rem >> 10;
    const int c0  = rem & (CDIM - 1);

    const unsigned int packed = *reinterpret_cast<const unsigned int*>(g_plane + i0);
    const float4 pr4 = *reinterpret_cast<const float4*>(pred + i0);
    const long long ob = ((long long)b * 2) * PER_BATCH + rem;
    const float4 oy4 = *reinterpret_cast<const float4*>(off + ob);
    const float4 ox4 = *reinterpret_cast<const float4*>(off + ob + PER_BATCH);

    const unsigned char* __restrict__ plane_b = g_plane + ((long long)b << 20);
    const float* __restrict__ inv_b = g_inv + b * MAX_INST;

    const float prs[4] = {pr4.x, pr4.y, pr4.z, pr4.w};
    const float oys[4] = {oy4.x, oy4.y, oy4.z, oy4.w};
    const float oxs[4] = {ox4.x, ox4.y, ox4.z, ox4.w};
    const float rf = (float)r;

    float pw[4], w0[4], w1[4];
    #pragma unroll
    for (int k = 0; k < 4; ++k) {
        const unsigned s = (packed >> (8 * k)) & 0xFFu;
        const int g = (int)(s & 0xFu);
        float w = 0.0f, agree_w = 0.0f;
        if (s & 0x10u) {                         // valid
            w = __ldg(&inv_b[g]);
            // round-half-to-even matches jnp.round
            float tyf = rintf(rf + oys[k]);
            float txf = rintf((float)(c0 + k) + oxs[k]);
            tyf = fminf(fmaxf(tyf, 0.0f), (float)(RDIM - 1));
            txf = fminf(fmaxf(txf, 0.0f), (float)(CDIM - 1));
            const unsigned tb = __ldg(&plane_b[((int)tyf << 10) + (int)txf]);
            agree_w = ((int)(tb & 0xFu) == g) ? w : 0.0f;
        }
        pw[k] = w * sigmoidf_fast(prs[k]);
        w0[k] = agree_w * oys[k];
        w1[k] = agree_w * oxs[k];
    }

    *reinterpret_cast<float4*>(out_pw + i0)             = make_float4(pw[0], pw[1], pw[2], pw[3]);
    *reinterpret_cast<float4*>(out_ow + ob)             = make_float4(w0[0], w0[1], w0[2], w0[3]);
    *reinterpret_cast<float4*>(out_ow + ob + PER_BATCH) = make_float4(w1[0], w1[1], w1[2], w1[3]);
}

extern "C" void kernel_launch(void* const* d_in, const int* in_sizes, int n_in,
                              void* d_out, int out_size) {
    const int*   nz   = (const int*)  d_in[0];  // non_zeros_map (B,R,C) int32
    const float* pred = (const float*)d_in[1];  // pixel_pred    (B,R,C) f32
    const float* off  = (const float*)d_in[2];  // offset_pred   (B,2,R,C) f32
    const int*   gt   = (const int*)  d_in[3];  // pixel_gt      (B,R,C) int32

    const long long N = in_sizes[0];            // B*R*C
    float* out_pw = (float*)d_out;
    float* out_ow = (float*)d_out + N;

    dim3 grid1(BLKS_PER_B, BATCH);
    pc_count_kernel<<<grid1, TPB1>>>(nz, gt);
    pc_reduce_kernel<<<1, 1024>>>();
    pc_main_kernel<<<GRID3, TPB3>>>(pred, off, out_pw, out_ow);
}